// round 1
// baseline (speedup 1.0000x reference)
#include <cuda_runtime.h>
#include <math.h>

#define H 1024
#define P 8
#define MAX_B 2048

// ---------------- scratch (static device globals; no allocation) ----------------
__device__ float g_w[P];          // column sums of interference matrix
__device__ float g_cc[2];         // [0] = alpha^2/64, [1] = alpha*(1-alpha)/64
__device__ float g_Weff[H * H];   // sum_j w[j] * W_paths[j]
__device__ float g_M[H * H];      // W_input @ Weff
__device__ float g_mixed[MAX_B * H]; // x @ M

// ---------------- kernel A: scalars (alpha, w[j]) ----------------
__global__ void prep_kernel(const float* __restrict__ J, const float* __restrict__ t) {
    if (threadIdx.x != 0) return;
    float tv = t[0];
    float alpha = expf(-tv / 51.0f);
    alpha = fminf(fmaxf(alpha, 0.0f), 1.0f);
    float phase = 2.0f * 3.14159265358979323846f * 20.0f * tv / 1000.0f;
    float w[P];
#pragma unroll
    for (int j = 0; j < P; j++) w[j] = 0.0f;
    for (int i = 0; i < P; i++) {
        float row[P];
        float mx = -1e30f;
#pragma unroll
        for (int j = 0; j < P; j++) {
            float js = 0.5f * (J[i * P + j] + J[j * P + i]);
            row[j] = cosf(phase * js);
            mx = fmaxf(mx, row[j]);
        }
        float s = 0.0f;
#pragma unroll
        for (int j = 0; j < P; j++) { row[j] = expf(row[j] - mx); s += row[j]; }
        float inv = 1.0f / s;
#pragma unroll
        for (int j = 0; j < P; j++) w[j] += row[j] * inv;
    }
#pragma unroll
    for (int j = 0; j < P; j++) g_w[j] = w[j];
    g_cc[0] = alpha * alpha / 64.0f;
    g_cc[1] = alpha * (1.0f - alpha) / 64.0f;
}

// ---------------- kernel B: Weff = sum_j w[j] * W_paths[j] ----------------
__global__ void weff_kernel(const float4* __restrict__ Wp) {
    int i = blockIdx.x * blockDim.x + threadIdx.x;  // over H*H/4
    float4 acc = make_float4(0.f, 0.f, 0.f, 0.f);
#pragma unroll
    for (int j = 0; j < P; j++) {
        float wj = g_w[j];
        float4 v = Wp[(size_t)j * (H * H / 4) + i];
        acc.x = fmaf(wj, v.x, acc.x);
        acc.y = fmaf(wj, v.y, acc.y);
        acc.z = fmaf(wj, v.z, acc.z);
        acc.w = fmaf(wj, v.w, acc.w);
    }
    ((float4*)g_Weff)[i] = acc;
}

// ---------------- tiled fp32 SIMT GEMM (C = A @ B, row-major) ----------------
template <int BM, int BN, int BK, int TM, int TN>
__device__ __forceinline__ void gemm_body(const float* __restrict__ A,
                                          const float* __restrict__ B,
                                          float* __restrict__ C,
                                          int M, int N, int K) {
    constexpr int NT = (BM / TM) * (BN / TN);
    __shared__ float As[BK][BM + 4];  // +4 pad: conflict-free transposed stores
    __shared__ float Bs[BK][BN];

    const int tid = threadIdx.x;
    const int tcol = tid % (BN / TN);
    const int trow = tid / (BN / TN);

    const float* Ab = A + (size_t)blockIdx.y * BM * K;
    const float* Bb = B + (size_t)blockIdx.x * BN;

    float acc[TM][TN];
#pragma unroll
    for (int i = 0; i < TM; i++)
#pragma unroll
        for (int j = 0; j < TN; j++) acc[i][j] = 0.0f;

    const int aRow0 = tid / (BK / 4);
    const int aCol = (tid % (BK / 4)) * 4;
    const int bRow0 = tid / (BN / 4);
    const int bCol = (tid % (BN / 4)) * 4;
    constexpr int A_RSTRIDE = NT / (BK / 4);
    constexpr int B_RSTRIDE = NT / (BN / 4);

    for (int k0 = 0; k0 < K; k0 += BK) {
#pragma unroll
        for (int r = 0; r < BM; r += A_RSTRIDE) {
            int rr = r + aRow0;
            float4 v = *(const float4*)(Ab + (size_t)rr * K + k0 + aCol);
            As[aCol + 0][rr] = v.x;
            As[aCol + 1][rr] = v.y;
            As[aCol + 2][rr] = v.z;
            As[aCol + 3][rr] = v.w;
        }
#pragma unroll
        for (int r = 0; r < BK; r += B_RSTRIDE) {
            int rr = r + bRow0;
            *(float4*)(&Bs[rr][bCol]) = *(const float4*)(Bb + (size_t)(k0 + rr) * N + bCol);
        }
        __syncthreads();
#pragma unroll
        for (int kk = 0; kk < BK; kk++) {
            float a[TM], b[TN];
#pragma unroll
            for (int i = 0; i < TM; i += 4)
                *(float4*)&a[i] = *(const float4*)&As[kk][trow * TM + i];
#pragma unroll
            for (int j = 0; j < TN; j += 4)
                *(float4*)&b[j] = *(const float4*)&Bs[kk][tcol * TN + j];
#pragma unroll
            for (int i = 0; i < TM; i++)
#pragma unroll
                for (int j = 0; j < TN; j++)
                    acc[i][j] = fmaf(a[i], b[j], acc[i][j]);
        }
        __syncthreads();
    }

    float* Cb = C + (size_t)(blockIdx.y * BM + trow * TM) * N + blockIdx.x * BN + tcol * TN;
#pragma unroll
    for (int i = 0; i < TM; i++) {
#pragma unroll
        for (int j = 0; j < TN; j += 4) {
            float4 v = make_float4(acc[i][j], acc[i][j + 1], acc[i][j + 2], acc[i][j + 3]);
            *(float4*)(Cb + (size_t)i * N + j) = v;
        }
    }
}

// GEMM-C: M = W_input @ Weff  (1024x1024x1024). 64x64 tiles -> 256 blocks (fills chip).
__global__ void __launch_bounds__(256) gemm_c_kernel(const float* __restrict__ A) {
    gemm_body<64, 64, 16, 4, 4>(A, g_Weff, g_M, H, H, H);
}

// GEMM-D: mixed = x @ M  (Bx1024x1024). 128x128 tiles -> B/128 * 8 blocks.
__global__ void __launch_bounds__(256) gemm_d_kernel(const float* __restrict__ X, int M) {
    gemm_body<128, 128, 16, 8, 8>(X, g_M, g_mixed, M, H, H);
}

// ---------------- kernel E: epilogue blend ----------------
// out[b,h] = cc0 * sum_j w[j]*coh[b,j,h] + cc1 * mixed[b,h]
__global__ void epilogue_kernel(const float4* __restrict__ coh, float4* __restrict__ out, int n4) {
    int i = blockIdx.x * blockDim.x + threadIdx.x;  // over B*H/4
    if (i >= n4) return;
    int b = i >> 8;        // H/4 = 256
    int h4 = i & 255;
    const float4* cp = coh + (size_t)b * (P * (H / 4)) + h4;
    float c0 = g_cc[0], c1 = g_cc[1];
    float4 acc = make_float4(0.f, 0.f, 0.f, 0.f);
#pragma unroll
    for (int j = 0; j < P; j++) {
        float wj = g_w[j];
        float4 v = cp[j * (H / 4)];
        acc.x = fmaf(wj, v.x, acc.x);
        acc.y = fmaf(wj, v.y, acc.y);
        acc.z = fmaf(wj, v.z, acc.z);
        acc.w = fmaf(wj, v.w, acc.w);
    }
    float4 m = ((const float4*)g_mixed)[i];
    out[i] = make_float4(c0 * acc.x + c1 * m.x,
                         c0 * acc.y + c1 * m.y,
                         c0 * acc.z + c1 * m.z,
                         c0 * acc.w + c1 * m.w);
}

// ---------------- launch ----------------
extern "C" void kernel_launch(void* const* d_in, const int* in_sizes, int n_in,
                              void* d_out, int out_size) {
    const float* x       = (const float*)d_in[0];  // [B, 1024]
    const float* W_input = (const float*)d_in[1];  // [1024, 1024]
    const float* W_paths = (const float*)d_in[2];  // [8, 1024, 1024]
    const float* J       = (const float*)d_in[3];  // [8, 8]
    const float* coh     = (const float*)d_in[4];  // [B, 8, 1024]
    const float* t       = (const float*)d_in[5];  // [1]

    int B = in_sizes[0] / H;  // 2048

    prep_kernel<<<1, 32>>>(J, t);
    weff_kernel<<<(H * H / 4) / 256, 256>>>((const float4*)W_paths);
    gemm_c_kernel<<<dim3(H / 64, H / 64), 256>>>(W_input);
    gemm_d_kernel<<<dim3(H / 128, B / 128), 256>>>(x, B);
    int n4 = B * H / 4;
    epilogue_kernel<<<(n4 + 255) / 256, 256>>>((const float4*)coh, (float4*)d_out, n4);
}

// round 6
// speedup vs baseline: 1.9129x; 1.9129x over previous
#include <cuda_runtime.h>
#include <math.h>
#include <stdint.h>

#define H 1024
#define P 8

// GEMM tiling
#define BM 128
#define BN 128
#define BK 32
#define NSTAGE 3
#define NC (H / BK)          // 32 K-chunks
#define SA 36                // A smem row stride (floats): bank-conflict-free frags
#define SB 136               // B smem row stride (floats)
#define A_F (BM * SA)        // 4608 floats
#define B_F (BK * SB)        // 4352 floats
#define STAGE_F (A_F + B_F)  // 8960 floats
#define SMEM_DYN (NSTAGE * STAGE_F * 4)  // 107520 bytes

// ---------------- scratch ----------------
__device__ float g_w[P];
__device__ float g_cc[2];
__device__ float g_Weff[H * H];
__device__ float g_M[H * H];

// ---------------- helpers ----------------
__device__ __forceinline__ uint32_t smem_u32(const void* p) {
    uint32_t a;
    asm("{ .reg .u64 t; cvta.to.shared.u64 t, %1; cvt.u32.u64 %0, t; }" : "=r"(a) : "l"(p));
    return a;
}
__device__ __forceinline__ uint32_t to_tf32(float f) {
    uint32_t u;
    asm("cvt.rna.tf32.f32 %0, %1;" : "=r"(u) : "f"(f));
    return u;
}
#define CPASYNC16(s, g) asm volatile("cp.async.cg.shared.global [%0], [%1], 16;" :: "r"(s), "l"(g) : "memory")
#define CPCOMMIT()      asm volatile("cp.async.commit_group;" ::: "memory")
#define CPWAIT2()       asm volatile("cp.async.wait_group 2;" ::: "memory")

__device__ __forceinline__ void mma_tf32(float* d, const uint32_t* a, const uint32_t* b) {
    asm volatile(
        "mma.sync.aligned.m16n8k8.row.col.f32.tf32.tf32.f32 "
        "{%0,%1,%2,%3}, {%4,%5,%6,%7}, {%8,%9}, {%0,%1,%2,%3};"
        : "+f"(d[0]), "+f"(d[1]), "+f"(d[2]), "+f"(d[3])
        : "r"(a[0]), "r"(a[1]), "r"(a[2]), "r"(a[3]), "r"(b[0]), "r"(b[1]));
}

// ---------------- kernel A: scalars ----------------
__global__ void prep_kernel(const float* __restrict__ J, const float* __restrict__ t) {
    if (threadIdx.x != 0) return;
    float tv = t[0];
    float alpha = expf(-tv / 51.0f);
    alpha = fminf(fmaxf(alpha, 0.0f), 1.0f);
    float phase = 2.0f * 3.14159265358979323846f * 20.0f * tv / 1000.0f;
    float w[P];
#pragma unroll
    for (int j = 0; j < P; j++) w[j] = 0.0f;
    for (int i = 0; i < P; i++) {
        float row[P];
        float mx = -1e30f;
#pragma unroll
        for (int j = 0; j < P; j++) {
            float js = 0.5f * (J[i * P + j] + J[j * P + i]);
            row[j] = cosf(phase * js);
            mx = fmaxf(mx, row[j]);
        }
        float s = 0.0f;
#pragma unroll
        for (int j = 0; j < P; j++) { row[j] = expf(row[j] - mx); s += row[j]; }
        float inv = 1.0f / s;
#pragma unroll
        for (int j = 0; j < P; j++) w[j] += row[j] * inv;
    }
#pragma unroll
    for (int j = 0; j < P; j++) g_w[j] = w[j];
    g_cc[0] = alpha * alpha / 64.0f;
    g_cc[1] = alpha * (1.0f - alpha) / 64.0f;
}

// ---------------- kernel B: Weff = sum_j w[j] * W_paths[j] ----------------
__global__ void weff_kernel(const float4* __restrict__ Wp) {
    int i = blockIdx.x * blockDim.x + threadIdx.x;
    float4 acc = make_float4(0.f, 0.f, 0.f, 0.f);
#pragma unroll
    for (int j = 0; j < P; j++) {
        float wj = g_w[j];
        float4 v = Wp[(size_t)j * (H * H / 4) + i];
        acc.x = fmaf(wj, v.x, acc.x);
        acc.y = fmaf(wj, v.y, acc.y);
        acc.z = fmaf(wj, v.z, acc.z);
        acc.w = fmaf(wj, v.w, acc.w);
    }
    ((float4*)g_Weff)[i] = acc;
}

// ---------------- tf32 mma.sync GEMM: C = A(MxK) @ B(KxN), K=N=1024 ----------------
// Warp layout: 8 warps = 4 (m) x 2 (n); warp tile 32x64; mma m16n8k8.
// MODE 0: store C.  MODE 1: fused epilogue  out = cc0*sum_j w_j*coh + cc1*acc.
template <int MODE>
__global__ void __launch_bounds__(256) gemm_mma(const float* __restrict__ A,
                                                const float* __restrict__ Bm,
                                                float* __restrict__ C,
                                                const float* __restrict__ coh) {
    extern __shared__ float sm[];
    const int tid = threadIdx.x;
    const int wid = tid >> 5;
    const int lane = tid & 31;
    const int g = lane >> 2;   // 0..7
    const int tg = lane & 3;   // 0..3
    const int warp_m = wid & 3;      // 0..3
    const int warp_n = wid >> 2;     // 0..1
    const int m0w = warp_m * 32;
    const int n0w = warp_n * 64;
    const int m0 = blockIdx.y * BM;
    const int n0 = blockIdx.x * BN;

    float acc[2][8][4];
#pragma unroll
    for (int mt = 0; mt < 2; mt++)
#pragma unroll
        for (int nt = 0; nt < 8; nt++)
#pragma unroll
            for (int q = 0; q < 4; q++) acc[mt][nt][q] = 0.0f;

    // ---- async tile loader ----
    auto load_tile = [&](int c) {
        int s = c % NSTAGE;
        float* As = sm + s * STAGE_F;
        float* Bs = As + A_F;
        int k0 = c * BK;
        // A: 128 rows x 32 floats -> As[row][k], stride SA
#pragma unroll
        for (int i = 0; i < 4; i++) {
            int v = tid + i * 256;
            int row = v >> 3, c4 = v & 7;
            const float* src = A + (size_t)(m0 + row) * H + k0 + c4 * 4;
            CPASYNC16(smem_u32(As + row * SA + c4 * 4), src);
        }
        // B: 32 rows x 128 floats -> Bs[k][n], stride SB
#pragma unroll
        for (int i = 0; i < 4; i++) {
            int v = tid + i * 256;
            int row = v >> 5, c4 = v & 31;
            const float* src = Bm + (size_t)(k0 + row) * H + n0 + c4 * 4;
            CPASYNC16(smem_u32(Bs + row * SB + c4 * 4), src);
        }
    };

    // prologue
#pragma unroll
    for (int c = 0; c < NSTAGE; c++) {
        load_tile(c);
        CPCOMMIT();
    }

    // mainloop
    for (int c = 0; c < NC; c++) {
        int s = c % NSTAGE;
        const float* As = sm + s * STAGE_F;
        const float* Bs = As + A_F;
        CPWAIT2();
        __syncthreads();
#pragma unroll
        for (int ks = 0; ks < 4; ks++) {
            uint32_t af[2][4];
#pragma unroll
            for (int mt = 0; mt < 2; mt++) {
                const float* ap = As + (m0w + mt * 16 + g) * SA + ks * 8 + tg;
                af[mt][0] = to_tf32(ap[0]);
                af[mt][1] = to_tf32(ap[8 * SA]);
                af[mt][2] = to_tf32(ap[4]);
                af[mt][3] = to_tf32(ap[8 * SA + 4]);
            }
            uint32_t bf[8][2];
#pragma unroll
            for (int nt = 0; nt < 8; nt++) {
                const float* bp = Bs + (ks * 8 + tg) * SB + n0w + nt * 8 + g;
                bf[nt][0] = to_tf32(bp[0]);
                bf[nt][1] = to_tf32(bp[4 * SB]);
            }
#pragma unroll
            for (int mt = 0; mt < 2; mt++)
#pragma unroll
                for (int nt = 0; nt < 8; nt++)
                    mma_tf32(acc[mt][nt], af[mt], bf[nt]);
        }
        __syncthreads();
        int nx = c + NSTAGE;
        if (nx < NC) load_tile(nx);
        CPCOMMIT();  // commit every iter (possibly empty) to keep group accounting uniform
    }

    // ---- epilogue ----
    if (MODE == 0) {
#pragma unroll
        for (int mt = 0; mt < 2; mt++) {
            int r0 = m0 + m0w + mt * 16 + g;
#pragma unroll
            for (int nt = 0; nt < 8; nt++) {
                int col = n0 + n0w + nt * 8 + 2 * tg;
                *(float2*)&C[(size_t)r0 * H + col] = make_float2(acc[mt][nt][0], acc[mt][nt][1]);
                *(float2*)&C[(size_t)(r0 + 8) * H + col] = make_float2(acc[mt][nt][2], acc[mt][nt][3]);
            }
        }
    } else {
        float wreg[P];
#pragma unroll
        for (int j = 0; j < P; j++) wreg[j] = g_w[j];
        float cc0 = g_cc[0], cc1 = g_cc[1];
#pragma unroll
        for (int mt = 0; mt < 2; mt++) {
#pragma unroll
            for (int half = 0; half < 2; half++) {
                int r = m0 + m0w + mt * 16 + g + half * 8;
                const float* crow = coh + (size_t)r * (P * H);
#pragma unroll
                for (int nt = 0; nt < 8; nt++) {
                    int col = n0 + n0w + nt * 8 + 2 * tg;
                    float sx = 0.f, sy = 0.f;
#pragma unroll
                    for (int j = 0; j < P; j++) {
                        float2 cv = *(const float2*)&crow[j * H + col];
                        sx = fmaf(wreg[j], cv.x, sx);
                        sy = fmaf(wreg[j], cv.y, sy);
                    }
                    float2 o;
                    o.x = fmaf(cc1, acc[mt][nt][half * 2 + 0], cc0 * sx);
                    o.y = fmaf(cc1, acc[mt][nt][half * 2 + 1], cc0 * sy);
                    *(float2*)&C[(size_t)r * H + col] = o;
                }
            }
        }
    }
}

// ---------------- launch ----------------
extern "C" void kernel_launch(void* const* d_in, const int* in_sizes, int n_in,
                              void* d_out, int out_size) {
    const float* x       = (const float*)d_in[0];
    const float* W_input = (const float*)d_in[1];
    const float* W_paths = (const float*)d_in[2];
    const float* J       = (const float*)d_in[3];
    const float* coh     = (const float*)d_in[4];
    const float* t       = (const float*)d_in[5];

    int B = in_sizes[0] / H;

    cudaFuncSetAttribute(gemm_mma<0>, cudaFuncAttributeMaxDynamicSharedMemorySize, SMEM_DYN);
    cudaFuncSetAttribute(gemm_mma<1>, cudaFuncAttributeMaxDynamicSharedMemorySize, SMEM_DYN);

    float* Weff_p;
    float* M_p;
    cudaGetSymbolAddress((void**)&Weff_p, g_Weff);
    cudaGetSymbolAddress((void**)&M_p, g_M);

    prep_kernel<<<1, 32>>>(J, t);
    weff_kernel<<<(H * H / 4) / 256, 256>>>((const float4*)W_paths);
    // M = W_input @ Weff
    gemm_mma<0><<<dim3(H / BN, H / BM), 256, SMEM_DYN>>>(W_input, Weff_p, M_p, nullptr);
    // out = cc0*(w-weighted coherent sum) + cc1*(x @ M)
    gemm_mma<1><<<dim3(H / BN, B / BM), 256, SMEM_DYN>>>(x, M_p, (float*)d_out, coh);
}